// round 13
// baseline (speedup 1.0000x reference)
#include <cuda_runtime.h>

#define HH 1024
#define WW 1024
#define HW (HH*WW)
#define NT 256
#define NB4 (HW/4/NT)     // 1024 blocks: init, fused (4 px/thread)
#define NTR 256
#define NBR (HW/16/NTR)   // 256 blocks: reduce (16 px/thread)

// ---------------- constants ----------------
__constant__ float c_lam;
__constant__ float c_tau;
__constant__ float c_th;

// ---------------- device scratch ----------------
__device__ __align__(16) float g_rhoc[HW];
__device__ __align__(16) float g_gi0[HW];
__device__ __align__(16) float g_gi1[HW];
__device__ __align__(16) float g_u[2][2*HW];
__device__ __align__(16) float g_p[2][4*HW];
__device__ float g_partial[NB4];
__device__ unsigned int g_count;
__device__ float g_S;

__device__ __forceinline__ float4 ldg4(const float* p) { return *(const float4*)p; }
__device__ __forceinline__ float2 ldg2(const float* p) { return *(const float2*)p; }

// 4x256 tile mapping (256-thread kernels, 4 px/thread in-row)
__device__ __forceinline__ void tile_map256(int& y, int& x0, int& pix) {
    int ty = blockIdx.x >> 2;
    int tx = (blockIdx.x & 3) << 8;
    y  = (ty << 2) + (threadIdx.x >> 6);
    x0 = tx + ((threadIdx.x & 63) << 2);
    pix = (y << 10) + x0;
}

// Separable sobel: col pass s_c = t0+2t1+t2, d_c = t0-t2;
// gx = s_{c-1}-s_{c+1}; gy = d_{c-1}+2d_c+d_{c+1}

// ---------------- K0: rho_c, grad_im, AND u_1 = v(u=0) ----------------
__global__ void __launch_bounds__(NT) k_init(const float* __restrict__ x, float* __restrict__ uout) {
    int t4 = blockIdx.x * NT + threadIdx.x;
    int pix = t4 * 4;
    int y = pix >> 10, x0 = pix & (WW - 1);
    const float* __restrict__ x1 = x + HW;

    float s[6], d[6];
    #pragma unroll
    for (int r = 0; r < 3; r++) {
        int yy = y - 1 + r; bool vy = (yy >= 0 && yy < HH);
        const float* row = x1 + yy * WW;
        float l = (vy && x0 > 0) ? row[x0 - 1] : 0.f;
        float4 b = vy ? ldg4(row + x0) : make_float4(0.f,0.f,0.f,0.f);
        float rg = (vy && x0 < WW - 4) ? row[x0 + 4] : 0.f;
        float rw[6] = {l, b.x, b.y, b.z, b.w, rg};
        #pragma unroll
        for (int j = 0; j < 6; j++) {
            if (r == 0)      { s[j] = rw[j];        d[j] = rw[j]; }
            else if (r == 1) { s[j] += 2.f * rw[j]; }
            else             { s[j] += rw[j];       d[j] -= rw[j]; }
        }
    }

    float4 xc0 = ldg4(x + pix);
    float4 xc1 = ldg4(x1 + pix);
    float4 RC = make_float4(xc1.x-xc0.x, xc1.y-xc0.y, xc1.z-xc0.z, xc1.w-xc0.w);
    *(float4*)(g_rhoc + pix) = RC;

    float4 A, B;
    float* Ap = &A.x; float* Bp = &B.x; const float* rc = &RC.x;
    #pragma unroll
    for (int i = 0; i < 4; i++) {
        Ap[i] = s[i] - s[i + 2];
        Bp[i] = d[i] + 2.f * d[i + 1] + d[i + 2];
    }
    *(float4*)(g_gi0 + pix) = A;
    *(float4*)(g_gi1 + pix) = B;

    float tl = c_th * c_lam;
    float o0[4], o1[4];
    #pragma unroll
    for (int i = 0; i < 4; i++) {
        float gi0 = Ap[i], gi1 = Bp[i];
        float nrm = gi0*gi0 + gi1*gi1;
        float rho = rc[i];
        float a = fabsf(rho);
        float thv = tl * nrm;
        float a0 = 0.f, a1 = 0.f;
        if (a < thv) {
            float q = rho / nrm;
            a0 = -q * gi0; a1 = -q * gi1;
        } else if (a > thv) {
            float sg = (rho > 0.f) ? 1.f : ((rho < 0.f) ? -1.f : 0.f);
            float c = tl * sg;
            a0 = -c * gi0; a1 = -c * gi1;
        }
        o0[i] = a0; o1[i] = a1;
    }
    *(float4*)(uout + pix)      = make_float4(o0[0],o0[1],o0[2],o0[3]);
    *(float4*)(uout + HW + pix) = make_float4(o1[0],o1[1],o1[2],o1[3]);

    if (pix == 0) g_count = 0u;
}

// ---------------- K_R: S = sum |sobel(u)|, 16 px/thread, rolling window + shuffle halos ----------------
__global__ void __launch_bounds__(NTR) k_reduce(const float* __restrict__ u) {
    int bx = (blockIdx.x & 3) << 8;
    int by = (blockIdx.x >> 2) << 4;
    int tx = threadIdx.x & 63;
    int ty = threadIdx.x >> 6;
    int x0 = bx + (tx << 2);
    int y0 = by + (ty << 2);
    int lane = threadIdx.x & 31;
    bool hL = (x0 > 0), hR = (x0 < WW - 4);

    float acc = 0.f;
    #pragma unroll
    for (int comp = 0; comp < 2; comp++) {
        const float* __restrict__ up = u + comp * HW;
        float w[3][6];
        #pragma unroll
        for (int rr = 0; rr < 2; rr++) {
            int yy = y0 - 1 + rr;
            bool vy = (yy >= 0 && yy < HH);
            const float* row = up + yy * WW;
            float4 b = vy ? ldg4(row + x0) : make_float4(0.f,0.f,0.f,0.f);
            float lm = __shfl_up_sync(0xffffffffu, b.w, 1);
            float rp = __shfl_down_sync(0xffffffffu, b.x, 1);
            if (lane == 0)  lm = (vy && hL) ? row[x0 - 1] : 0.f;
            if (lane == 31) rp = (vy && hR) ? row[x0 + 4] : 0.f;
            w[rr][0]=lm; w[rr][1]=b.x; w[rr][2]=b.y; w[rr][3]=b.z; w[rr][4]=b.w; w[rr][5]=rp;
        }
        #pragma unroll
        for (int r = 0; r < 4; r++) {
            int yy = y0 + 1 + r;
            bool vy = (yy < HH);
            const float* row = up + yy * WW;
            float4 b = vy ? ldg4(row + x0) : make_float4(0.f,0.f,0.f,0.f);
            float lm = __shfl_up_sync(0xffffffffu, b.w, 1);
            float rp = __shfl_down_sync(0xffffffffu, b.x, 1);
            if (lane == 0)  lm = (vy && hL) ? row[x0 - 1] : 0.f;
            if (lane == 31) rp = (vy && hR) ? row[x0 + 4] : 0.f;
            int sb = (r + 2) % 3;
            w[sb][0]=lm; w[sb][1]=b.x; w[sb][2]=b.y; w[sb][3]=b.z; w[sb][4]=b.w; w[sb][5]=rp;

            int st = r % 3, sm_ = (r + 1) % 3;
            float s[6], d[6];
            #pragma unroll
            for (int j = 0; j < 6; j++) {
                s[j] = w[st][j] + 2.f * w[sm_][j] + w[sb][j];
                d[j] = w[st][j] - w[sb][j];
            }
            #pragma unroll
            for (int i = 0; i < 4; i++)
                acc += fabsf(s[i] - s[i + 2]) + fabsf(d[i] + 2.f * d[i + 1] + d[i + 2]);
        }
    }

    __shared__ float sm[NTR];
    int tid = threadIdx.x;
    sm[tid] = acc;
    __syncthreads();
    for (int s = NTR / 2; s > 0; s >>= 1) {
        if (tid < s) sm[tid] += sm[tid + s];
        __syncthreads();
    }
    __shared__ bool isLast;
    if (tid == 0) {
        g_partial[blockIdx.x] = sm[0];
        __threadfence();
        unsigned prev = atomicAdd(&g_count, 1u);
        isLast = (prev == gridDim.x - 1);
    }
    __syncthreads();
    if (isLast && tid < 32) {
        float s = 0.f;
        for (int i = tid; i < (int)gridDim.x; i += 32) s += g_partial[i];
        #pragma unroll
        for (int o = 16; o > 0; o >>= 1) s += __shfl_down_sync(0xffffffffu, s, o);
        if (tid == 0) { g_S = s; g_count = 0u; }
    }
}

// ---------------- K_F: fused p-recompute + u update, shuffle halos ----------------
// MODE 0: t==1 (p_in == 0). MODE 1: mid. MODE 2: last (no p write).
template<int MODE>
__global__ void __launch_bounds__(NT, 4) k_fused(const float* __restrict__ uin, float* __restrict__ uout,
                        const float* __restrict__ pin, float* __restrict__ pout) {
    int y, x0, pix;
    tile_map256(y, x0, pix);
    int lane = threadIdx.x & 31;
    bool hL = (x0 > 0), hR = (x0 < WW - 4);

    const float theta = c_th;
    const float tl = theta * c_lam;
    const float rr = c_tau / theta;
    const float inv = 1.f / (1.f + rr * g_S);

    // ---- u0: cols x0-2..x0+5 via own float4 + shuffles; rows y-1..y+1 ----
    float s0[8], d0[8];
    float u0c[4];
    #pragma unroll
    for (int r = 0; r < 3; r++) {
        int yy = y - 1 + r; bool vy = (yy >= 0 && yy < HH);
        const float* row = uin + yy * WW;
        float4 b = vy ? ldg4(row + x0) : make_float4(0.f,0.f,0.f,0.f);
        float lm2 = __shfl_up_sync(0xffffffffu, b.z, 1);
        float lm1 = __shfl_up_sync(0xffffffffu, b.w, 1);
        float rp4 = __shfl_down_sync(0xffffffffu, b.x, 1);
        float rp5 = __shfl_down_sync(0xffffffffu, b.y, 1);
        if (lane == 0) {
            float2 a = (vy && hL) ? ldg2(row + x0 - 2) : make_float2(0.f,0.f);
            lm2 = a.x; lm1 = a.y;
        }
        if (lane == 31) {
            float2 c = (vy && hR) ? ldg2(row + x0 + 4) : make_float2(0.f,0.f);
            rp4 = c.x; rp5 = c.y;
        }
        float rw[8] = {lm2, lm1, b.x, b.y, b.z, b.w, rp4, rp5};
        if (r == 1) { u0c[0]=rw[2]; u0c[1]=rw[3]; u0c[2]=rw[4]; u0c[3]=rw[5]; }
        #pragma unroll
        for (int j = 0; j < 8; j++) {
            if (r == 0)      { s0[j] = rw[j];        d0[j] = rw[j]; }
            else if (r == 1) { s0[j] += 2.f * rw[j]; }
            else             { s0[j] += rw[j];       d0[j] -= rw[j]; }
        }
    }
    float G00[4], G01[4];
    #pragma unroll
    for (int i = 0; i < 4; i++) {
        G00[i] = s0[i + 1] - s0[i + 3];
        G01[i] = d0[i + 1] + 2.f * d0[i + 2] + d0[i + 3];
    }
    float L00 = s0[0] - s0[2];
    float L01 = d0[0] + 2.f * d0[1] + d0[2];

    // ---- u1: cols x0-1..x0+4; rows y-2..y+1 ----
    float su[6], du[6], so[6], dn[6];
    float u1c[4];
    const float* __restrict__ uin1 = uin + HW;
    #pragma unroll
    for (int r = 0; r < 4; r++) {
        int yy = y - 2 + r; bool vy = (yy >= 0 && yy < HH);
        const float* row = uin1 + yy * WW;
        float4 b = vy ? ldg4(row + x0) : make_float4(0.f,0.f,0.f,0.f);
        float lm1 = __shfl_up_sync(0xffffffffu, b.w, 1);
        float rp4 = __shfl_down_sync(0xffffffffu, b.x, 1);
        if (lane == 0)  lm1 = (vy && hL) ? row[x0 - 1] : 0.f;
        if (lane == 31) rp4 = (vy && hR) ? row[x0 + 4] : 0.f;
        float rw[6] = {lm1, b.x, b.y, b.z, b.w, rp4};
        if (r == 2) { u1c[0]=rw[1]; u1c[1]=rw[2]; u1c[2]=rw[3]; u1c[3]=rw[4]; }
        #pragma unroll
        for (int j = 0; j < 6; j++) {
            if (r == 0)      { su[j] = rw[j];        du[j] = rw[j]; }
            else if (r == 1) { su[j] += 2.f * rw[j]; so[j] = rw[j]; dn[j] = rw[j]; }
            else if (r == 2) { su[j] += rw[j]; du[j] -= rw[j]; so[j] += 2.f * rw[j]; }
            else             { so[j] += rw[j];       dn[j] -= rw[j]; }
        }
    }
    float G10[4], G11[4], U10[4], U11[4];
    #pragma unroll
    for (int i = 0; i < 4; i++) {
        G10[i] = so[i] - so[i + 2];
        G11[i] = dn[i] + 2.f * dn[i + 1] + dn[i + 2];
        U10[i] = su[i] - su[i + 2];
        U11[i] = du[i] + 2.f * du[i + 1] + du[i + 2];
    }

    // ---- pointwise v update ----
    float4 GI0 = ldg4(g_gi0 + pix);
    float4 GI1 = ldg4(g_gi1 + pix);
    float4 RC  = ldg4(g_rhoc + pix);
    const float* gi0 = &GI0.x; const float* gi1 = &GI1.x; const float* rc = &RC.x;

    float v0[4], v1[4];
    #pragma unroll
    for (int i = 0; i < 4; i++) {
        float nrm = gi0[i]*gi0[i] + gi1[i]*gi1[i];
        float rho = rc[i] + gi0[i]*u0c[i] + gi1[i]*u1c[i];
        float a = fabsf(rho);
        float thv = tl * nrm;
        float a0 = u0c[i], a1 = u1c[i];
        if (a < thv) {
            float q = rho / nrm;
            a0 -= q * gi0[i]; a1 -= q * gi1[i];
        } else if (a > thv) {
            float sg = (rho > 0.f) ? 1.f : ((rho < 0.f) ? -1.f : 0.f);
            float c = tl * sg;
            a0 -= c * gi0[i]; a1 -= c * gi1[i];
        }
        v0[i] = a0; v1[i] = a1;
    }

    bool hasU = (y > 0);

    float np0[4], np1[4], np2[4], np3[4];
    float lft0, lft1;
    float pU2v[4], pU3v[4];

    if (MODE == 0) {
        #pragma unroll
        for (int i = 0; i < 4; i++) {
            np0[i] = rr * G00[i] * inv;
            np1[i] = rr * G01[i] * inv;
            np2[i] = rr * G10[i] * inv;
            np3[i] = rr * G11[i] * inv;
            pU2v[i] = hasU ? rr * U10[i] * inv : 0.f;
            pU3v[i] = hasU ? rr * U11[i] * inv : 0.f;
        }
        lft0 = hL ? rr * L00 * inv : 0.f;
        lft1 = hL ? rr * L01 * inv : 0.f;
    } else {
        float4 P0 = ldg4(pin + pix);
        float4 P1 = ldg4(pin + HW + pix);
        float4 P2 = ldg4(pin + 2*HW + pix);
        float4 P3 = ldg4(pin + 3*HW + pix);
        const float* p0 = &P0.x; const float* p1 = &P1.x;
        const float* p2 = &P2.x; const float* p3 = &P3.x;

        float4 PU2 = hasU ? ldg4(pin + 2*HW + pix - WW) : make_float4(0.f,0.f,0.f,0.f);
        float4 PU3 = hasU ? ldg4(pin + 3*HW + pix - WW) : make_float4(0.f,0.f,0.f,0.f);
        const float* pu2 = &PU2.x; const float* pu3 = &PU3.x;

        // left p halo via shuffle (pin[pix-1] = lane(i-1).P0.w)
        float pl0 = __shfl_up_sync(0xffffffffu, P0.w, 1);
        float pl1 = __shfl_up_sync(0xffffffffu, P1.w, 1);
        if (lane == 0) {
            pl0 = hL ? pin[pix - 1]      : 0.f;
            pl1 = hL ? pin[HW + pix - 1] : 0.f;
        }

        #pragma unroll
        for (int i = 0; i < 4; i++) {
            np0[i] = (p0[i] + rr * G00[i]) * inv;
            np1[i] = (p1[i] + rr * G01[i]) * inv;
            np2[i] = (p2[i] + rr * G10[i]) * inv;
            np3[i] = (p3[i] + rr * G11[i]) * inv;
            pU2v[i] = hasU ? (pu2[i] + rr * U10[i]) * inv : 0.f;
            pU3v[i] = hasU ? (pu3[i] + rr * U11[i]) * inv : 0.f;
        }
        lft0 = hL ? (pl0 + rr * L00) * inv : 0.f;
        lft1 = hL ? (pl1 + rr * L01) * inv : 0.f;
    }

    // wx = wy = (1,1): divergence = left + own + up + own
    float o0[4], o1[4];
    #pragma unroll
    for (int i = 0; i < 4; i++) {
        float pL0 = (i == 0) ? lft0 : np0[i-1];
        float pL1 = (i == 0) ? lft1 : np1[i-1];
        float d0v = pL0 + np0[i] + pU2v[i] + np2[i];
        float d1v = pL1 + np1[i] + pU3v[i] + np3[i];
        o0[i] = v0[i] + theta * d0v;
        o1[i] = v1[i] + theta * d1v;
    }

    *(float4*)(uout + pix)      = make_float4(o0[0],o0[1],o0[2],o0[3]);
    *(float4*)(uout + HW + pix) = make_float4(o1[0],o1[1],o1[2],o1[3]);

    if (MODE != 2) {
        *(float4*)(pout + pix)        = make_float4(np0[0],np0[1],np0[2],np0[3]);
        *(float4*)(pout + HW + pix)   = make_float4(np1[0],np1[1],np1[2],np1[3]);
        *(float4*)(pout + 2*HW + pix) = make_float4(np2[0],np2[1],np2[2],np2[3]);
        *(float4*)(pout + 3*HW + pix) = make_float4(np3[0],np3[1],np3[2],np3[3]);
    }
}

// ---------------- launch ----------------
extern "C" void kernel_launch(void* const* d_in, const int* in_sizes, int n_in,
                              void* d_out, int out_size) {
    const float* x   = (const float*)d_in[0];
    const float* lam = (const float*)d_in[4];
    const float* tau = (const float*)d_in[5];
    const float* th  = (const float*)d_in[6];
    float* out = (float*)d_out;

    cudaMemcpyToSymbolAsync(c_lam, lam, sizeof(float), 0, cudaMemcpyDeviceToDevice);
    cudaMemcpyToSymbolAsync(c_tau, tau, sizeof(float), 0, cudaMemcpyDeviceToDevice);
    cudaMemcpyToSymbolAsync(c_th,  th,  sizeof(float), 0, cudaMemcpyDeviceToDevice);

    float* ubase; cudaGetSymbolAddress((void**)&ubase, g_u);
    float* pbase; cudaGetSymbolAddress((void**)&pbase, g_p);
    float* ubuf[2] = { ubase, ubase + 2*HW };
    float* pbuf[2] = { pbase, pbase + 4*HW };

    k_init<<<NB4, NT>>>(x, ubuf[1]);

    for (int t = 1; t <= 9; t++) {
        k_reduce<<<NBR, NTR>>>(ubuf[t & 1]);
        float* uo = (t == 9) ? out : ubuf[(t + 1) & 1];
        if (t == 1)
            k_fused<0><<<NB4, NT>>>(ubuf[1], uo, nullptr, pbuf[1]);
        else if (t < 9)
            k_fused<1><<<NB4, NT>>>(ubuf[t & 1], uo, pbuf[(t + 1) & 1], pbuf[t & 1]);
        else
            k_fused<2><<<NB4, NT>>>(ubuf[t & 1], uo, pbuf[(t + 1) & 1], nullptr);
    }
}

// round 14
// speedup vs baseline: 1.1378x; 1.1378x over previous
#include <cuda_runtime.h>

#define HH 1024
#define WW 1024
#define HW (HH*WW)
#define NT 256
#define NB4 (HW/4/NT)     // 1024 blocks: init, fused (4 px/thread)
#define NTR 256
#define NBR (HW/8/NTR)    // 512 blocks: reduce (8 px/thread)

// ---------------- constants ----------------
__constant__ float c_lam;
__constant__ float c_tau;
__constant__ float c_th;

// ---------------- device scratch ----------------
__device__ __align__(16) float g_rhoc[HW];
__device__ __align__(16) float g_gi0[HW];
__device__ __align__(16) float g_gi1[HW];
__device__ __align__(16) float g_u[2][2*HW];
__device__ __align__(16) float g_p[2][4*HW];
__device__ float g_partial[NB4];
__device__ unsigned int g_count;
__device__ float g_S;

__device__ __forceinline__ float4 ldg4(const float* p) { return *(const float4*)p; }
__device__ __forceinline__ float2 ldg2(const float* p) { return *(const float2*)p; }

// 4x256 tile mapping (256-thread kernels, 4 px/thread in-row)
__device__ __forceinline__ void tile_map256(int& y, int& x0, int& pix) {
    int ty = blockIdx.x >> 2;
    int tx = (blockIdx.x & 3) << 8;
    y  = (ty << 2) + (threadIdx.x >> 6);
    x0 = tx + ((threadIdx.x & 63) << 2);
    pix = (y << 10) + x0;
}

// Separable sobel: col pass s_c = t0+2t1+t2, d_c = t0-t2;
// gx = s_{c-1}-s_{c+1}; gy = d_{c-1}+2d_c+d_{c+1}

// ---------------- K0: rho_c, grad_im, AND u_1 = v(u=0) ----------------
__global__ void __launch_bounds__(NT) k_init(const float* __restrict__ x, float* __restrict__ uout) {
    int t4 = blockIdx.x * NT + threadIdx.x;
    int pix = t4 * 4;
    int y = pix >> 10, x0 = pix & (WW - 1);
    const float* __restrict__ x1 = x + HW;

    float s[6], d[6];
    #pragma unroll
    for (int r = 0; r < 3; r++) {
        int yy = y - 1 + r; bool vy = (yy >= 0 && yy < HH);
        const float* row = x1 + yy * WW;
        float l = (vy && x0 > 0) ? row[x0 - 1] : 0.f;
        float4 b = vy ? ldg4(row + x0) : make_float4(0.f,0.f,0.f,0.f);
        float rg = (vy && x0 < WW - 4) ? row[x0 + 4] : 0.f;
        float rw[6] = {l, b.x, b.y, b.z, b.w, rg};
        #pragma unroll
        for (int j = 0; j < 6; j++) {
            if (r == 0)      { s[j] = rw[j];        d[j] = rw[j]; }
            else if (r == 1) { s[j] += 2.f * rw[j]; }
            else             { s[j] += rw[j];       d[j] -= rw[j]; }
        }
    }

    float4 xc0 = ldg4(x + pix);
    float4 xc1 = ldg4(x1 + pix);
    float4 RC = make_float4(xc1.x-xc0.x, xc1.y-xc0.y, xc1.z-xc0.z, xc1.w-xc0.w);
    *(float4*)(g_rhoc + pix) = RC;

    float4 A, B;
    float* Ap = &A.x; float* Bp = &B.x; const float* rc = &RC.x;
    #pragma unroll
    for (int i = 0; i < 4; i++) {
        Ap[i] = s[i] - s[i + 2];
        Bp[i] = d[i] + 2.f * d[i + 1] + d[i + 2];
    }
    *(float4*)(g_gi0 + pix) = A;
    *(float4*)(g_gi1 + pix) = B;

    float tl = c_th * c_lam;
    float o0[4], o1[4];
    #pragma unroll
    for (int i = 0; i < 4; i++) {
        float gi0 = Ap[i], gi1 = Bp[i];
        float nrm = gi0*gi0 + gi1*gi1;
        float rho = rc[i];
        float a = fabsf(rho);
        float thv = tl * nrm;
        float a0 = 0.f, a1 = 0.f;
        if (a < thv) {
            float q = rho / nrm;
            a0 = -q * gi0; a1 = -q * gi1;
        } else if (a > thv) {
            float sg = (rho > 0.f) ? 1.f : ((rho < 0.f) ? -1.f : 0.f);
            float c = tl * sg;
            a0 = -c * gi0; a1 = -c * gi1;
        }
        o0[i] = a0; o1[i] = a1;
    }
    *(float4*)(uout + pix)      = make_float4(o0[0],o0[1],o0[2],o0[3]);
    *(float4*)(uout + HW + pix) = make_float4(o1[0],o1[1],o1[2],o1[3]);

    if (pix == 0) g_count = 0u;
}

// ---------------- K_R: S = sum |sobel(u)|, 8 px/thread (2 rows x 4 cols), rolling window ----------------
__global__ void __launch_bounds__(NTR) k_reduce(const float* __restrict__ u) {
    // block tile: 8 rows x 256 cols; thread: 2 rows x 4 cols; grid 512
    int bx = (blockIdx.x & 3) << 8;
    int by = (blockIdx.x >> 2) << 3;
    int tx = threadIdx.x & 63;
    int ty = threadIdx.x >> 6;
    int x0 = bx + (tx << 2);
    int y0 = by + (ty << 1);
    bool hL = (x0 > 0), hR = (x0 < WW - 4);

    float acc = 0.f;
    #pragma unroll
    for (int comp = 0; comp < 2; comp++) {
        const float* __restrict__ up = u + comp * HW;
        float w[3][6];
        // preload rows y0-1, y0 into slots 0,1
        #pragma unroll
        for (int rr = 0; rr < 2; rr++) {
            int yy = y0 - 1 + rr;
            bool vy = (yy >= 0 && yy < HH);
            const float* row = up + yy * WW;
            float l = (vy && hL) ? row[x0 - 1] : 0.f;
            float4 b = vy ? ldg4(row + x0) : make_float4(0.f,0.f,0.f,0.f);
            float rg = (vy && hR) ? row[x0 + 4] : 0.f;
            w[rr][0]=l; w[rr][1]=b.x; w[rr][2]=b.y; w[rr][3]=b.z; w[rr][4]=b.w; w[rr][5]=rg;
        }
        #pragma unroll
        for (int r = 0; r < 2; r++) {
            int yy = y0 + 1 + r;                    // >= 1 always
            bool vy = (yy < HH);
            const float* row = up + yy * WW;
            float l = (vy && hL) ? row[x0 - 1] : 0.f;
            float4 b = vy ? ldg4(row + x0) : make_float4(0.f,0.f,0.f,0.f);
            float rg = (vy && hR) ? row[x0 + 4] : 0.f;
            int sb = (r + 2) % 3;
            w[sb][0]=l; w[sb][1]=b.x; w[sb][2]=b.y; w[sb][3]=b.z; w[sb][4]=b.w; w[sb][5]=rg;

            int st = r % 3, sm_ = (r + 1) % 3;
            float s[6], d[6];
            #pragma unroll
            for (int j = 0; j < 6; j++) {
                s[j] = w[st][j] + 2.f * w[sm_][j] + w[sb][j];
                d[j] = w[st][j] - w[sb][j];
            }
            #pragma unroll
            for (int i = 0; i < 4; i++)
                acc += fabsf(s[i] - s[i + 2]) + fabsf(d[i] + 2.f * d[i + 1] + d[i + 2]);
        }
    }

    __shared__ float sm[NTR];
    int tid = threadIdx.x;
    sm[tid] = acc;
    __syncthreads();
    for (int s = NTR / 2; s > 0; s >>= 1) {
        if (tid < s) sm[tid] += sm[tid + s];
        __syncthreads();
    }
    __shared__ bool isLast;
    if (tid == 0) {
        g_partial[blockIdx.x] = sm[0];
        __threadfence();
        unsigned prev = atomicAdd(&g_count, 1u);
        isLast = (prev == gridDim.x - 1);
    }
    __syncthreads();
    if (isLast && tid < 32) {
        float s = 0.f;
        for (int i = tid; i < (int)gridDim.x; i += 32) s += g_partial[i];
        #pragma unroll
        for (int o = 16; o > 0; o >>= 1) s += __shfl_down_sync(0xffffffffu, s, o);
        if (tid == 0) { g_S = s; g_count = 0u; }
    }
}

// ---------------- K_F: fused p-recompute + u update, 4 px/thread, 4x256 tiles ----------------
// MODE 0: t==1 (p_in == 0). MODE 1: mid. MODE 2: last (no p write).
template<int MODE>
__global__ void __launch_bounds__(NT, 4) k_fused(const float* __restrict__ uin, float* __restrict__ uout,
                        const float* __restrict__ pin, float* __restrict__ pout) {
    int y, x0, pix;
    tile_map256(y, x0, pix);

    const float theta = c_th;
    const float tl = theta * c_lam;
    const float rr = c_tau / theta;
    const float inv = 1.f / (1.f + rr * g_S);

    // ---- u0 component: cols x0-2..x0+5 (8), rows y-1..y+1 ----
    float s0[8], d0[8];
    float u0c[4];
    #pragma unroll
    for (int r = 0; r < 3; r++) {
        int yy = y - 1 + r; bool vy = (yy >= 0 && yy < HH);
        const float* row = uin + yy * WW;
        float2 a = (vy && x0 > 0) ? ldg2(row + x0 - 2) : make_float2(0.f,0.f);
        float4 b = vy ? ldg4(row + x0) : make_float4(0.f,0.f,0.f,0.f);
        float2 c = (vy && x0 < WW - 4) ? ldg2(row + x0 + 4) : make_float2(0.f,0.f);
        float rw[8] = {a.x, a.y, b.x, b.y, b.z, b.w, c.x, c.y};
        if (r == 1) { u0c[0]=rw[2]; u0c[1]=rw[3]; u0c[2]=rw[4]; u0c[3]=rw[5]; }
        #pragma unroll
        for (int j = 0; j < 8; j++) {
            if (r == 0)      { s0[j] = rw[j];        d0[j] = rw[j]; }
            else if (r == 1) { s0[j] += 2.f * rw[j]; }
            else             { s0[j] += rw[j];       d0[j] -= rw[j]; }
        }
    }
    float G00[4], G01[4];
    #pragma unroll
    for (int i = 0; i < 4; i++) {
        G00[i] = s0[i + 1] - s0[i + 3];
        G01[i] = d0[i + 1] + 2.f * d0[i + 2] + d0[i + 3];
    }
    float L00 = s0[0] - s0[2];
    float L01 = d0[0] + 2.f * d0[1] + d0[2];

    // ---- u1 component: cols x0-1..x0+4 (6), rows y-2..y+1 ----
    float su[6], du[6], so[6], dn[6];
    float u1c[4];
    const float* __restrict__ uin1 = uin + HW;
    #pragma unroll
    for (int r = 0; r < 4; r++) {
        int yy = y - 2 + r; bool vy = (yy >= 0 && yy < HH);
        const float* row = uin1 + yy * WW;
        float l = (vy && x0 > 0) ? row[x0 - 1] : 0.f;
        float4 b = vy ? ldg4(row + x0) : make_float4(0.f,0.f,0.f,0.f);
        float rg = (vy && x0 < WW - 4) ? row[x0 + 4] : 0.f;
        float rw[6] = {l, b.x, b.y, b.z, b.w, rg};
        if (r == 2) { u1c[0]=rw[1]; u1c[1]=rw[2]; u1c[2]=rw[3]; u1c[3]=rw[4]; }
        #pragma unroll
        for (int j = 0; j < 6; j++) {
            if (r == 0)      { su[j] = rw[j];        du[j] = rw[j]; }
            else if (r == 1) { su[j] += 2.f * rw[j]; so[j] = rw[j]; dn[j] = rw[j]; }
            else if (r == 2) { su[j] += rw[j]; du[j] -= rw[j]; so[j] += 2.f * rw[j]; }
            else             { so[j] += rw[j];       dn[j] -= rw[j]; }
        }
    }
    float G10[4], G11[4], U10[4], U11[4];
    #pragma unroll
    for (int i = 0; i < 4; i++) {
        G10[i] = so[i] - so[i + 2];
        G11[i] = dn[i] + 2.f * dn[i + 1] + dn[i + 2];
        U10[i] = su[i] - su[i + 2];
        U11[i] = du[i] + 2.f * du[i + 1] + du[i + 2];
    }

    // ---- pointwise v update ----
    float4 GI0 = ldg4(g_gi0 + pix);
    float4 GI1 = ldg4(g_gi1 + pix);
    float4 RC  = ldg4(g_rhoc + pix);
    const float* gi0 = &GI0.x; const float* gi1 = &GI1.x; const float* rc = &RC.x;

    float v0[4], v1[4];
    #pragma unroll
    for (int i = 0; i < 4; i++) {
        float nrm = gi0[i]*gi0[i] + gi1[i]*gi1[i];
        float rho = rc[i] + gi0[i]*u0c[i] + gi1[i]*u1c[i];
        float a = fabsf(rho);
        float thv = tl * nrm;
        float a0 = u0c[i], a1 = u1c[i];
        if (a < thv) {
            float q = rho / nrm;
            a0 -= q * gi0[i]; a1 -= q * gi1[i];
        } else if (a > thv) {
            float sg = (rho > 0.f) ? 1.f : ((rho < 0.f) ? -1.f : 0.f);
            float c = tl * sg;
            a0 -= c * gi0[i]; a1 -= c * gi1[i];
        }
        v0[i] = a0; v1[i] = a1;
    }

    bool hasU = (y > 0);
    bool hasL = (x0 > 0);

    float np0[4], np1[4], np2[4], np3[4];
    float lft0, lft1;
    float pU2v[4], pU3v[4];

    if (MODE == 0) {
        #pragma unroll
        for (int i = 0; i < 4; i++) {
            np0[i] = rr * G00[i] * inv;
            np1[i] = rr * G01[i] * inv;
            np2[i] = rr * G10[i] * inv;
            np3[i] = rr * G11[i] * inv;
            pU2v[i] = hasU ? rr * U10[i] * inv : 0.f;
            pU3v[i] = hasU ? rr * U11[i] * inv : 0.f;
        }
        lft0 = hasL ? rr * L00 * inv : 0.f;
        lft1 = hasL ? rr * L01 * inv : 0.f;
    } else {
        float4 P0 = ldg4(pin + pix);
        float4 P1 = ldg4(pin + HW + pix);
        float4 P2 = ldg4(pin + 2*HW + pix);
        float4 P3 = ldg4(pin + 3*HW + pix);
        const float* p0 = &P0.x; const float* p1 = &P1.x;
        const float* p2 = &P2.x; const float* p3 = &P3.x;

        float4 PU2 = hasU ? ldg4(pin + 2*HW + pix - WW) : make_float4(0.f,0.f,0.f,0.f);
        float4 PU3 = hasU ? ldg4(pin + 3*HW + pix - WW) : make_float4(0.f,0.f,0.f,0.f);
        const float* pu2 = &PU2.x; const float* pu3 = &PU3.x;

        float pl0 = hasL ? pin[pix - 1]      : 0.f;
        float pl1 = hasL ? pin[HW + pix - 1] : 0.f;

        #pragma unroll
        for (int i = 0; i < 4; i++) {
            np0[i] = (p0[i] + rr * G00[i]) * inv;
            np1[i] = (p1[i] + rr * G01[i]) * inv;
            np2[i] = (p2[i] + rr * G10[i]) * inv;
            np3[i] = (p3[i] + rr * G11[i]) * inv;
            pU2v[i] = hasU ? (pu2[i] + rr * U10[i]) * inv : 0.f;
            pU3v[i] = hasU ? (pu3[i] + rr * U11[i]) * inv : 0.f;
        }
        lft0 = hasL ? (pl0 + rr * L00) * inv : 0.f;
        lft1 = hasL ? (pl1 + rr * L01) * inv : 0.f;
    }

    // wx = wy = (1,1): divergence = left + own + up + own
    float o0[4], o1[4];
    #pragma unroll
    for (int i = 0; i < 4; i++) {
        float pL0 = (i == 0) ? lft0 : np0[i-1];
        float pL1 = (i == 0) ? lft1 : np1[i-1];
        float d0v = pL0 + np0[i] + pU2v[i] + np2[i];
        float d1v = pL1 + np1[i] + pU3v[i] + np3[i];
        o0[i] = v0[i] + theta * d0v;
        o1[i] = v1[i] + theta * d1v;
    }

    *(float4*)(uout + pix)      = make_float4(o0[0],o0[1],o0[2],o0[3]);
    *(float4*)(uout + HW + pix) = make_float4(o1[0],o1[1],o1[2],o1[3]);

    if (MODE != 2) {
        *(float4*)(pout + pix)        = make_float4(np0[0],np0[1],np0[2],np0[3]);
        *(float4*)(pout + HW + pix)   = make_float4(np1[0],np1[1],np1[2],np1[3]);
        *(float4*)(pout + 2*HW + pix) = make_float4(np2[0],np2[1],np2[2],np2[3]);
        *(float4*)(pout + 3*HW + pix) = make_float4(np3[0],np3[1],np3[2],np3[3]);
    }
}

// ---------------- launch ----------------
extern "C" void kernel_launch(void* const* d_in, const int* in_sizes, int n_in,
                              void* d_out, int out_size) {
    const float* x   = (const float*)d_in[0];
    const float* lam = (const float*)d_in[4];
    const float* tau = (const float*)d_in[5];
    const float* th  = (const float*)d_in[6];
    float* out = (float*)d_out;

    cudaMemcpyToSymbolAsync(c_lam, lam, sizeof(float), 0, cudaMemcpyDeviceToDevice);
    cudaMemcpyToSymbolAsync(c_tau, tau, sizeof(float), 0, cudaMemcpyDeviceToDevice);
    cudaMemcpyToSymbolAsync(c_th,  th,  sizeof(float), 0, cudaMemcpyDeviceToDevice);

    float* ubase; cudaGetSymbolAddress((void**)&ubase, g_u);
    float* pbase; cudaGetSymbolAddress((void**)&pbase, g_p);
    float* ubuf[2] = { ubase, ubase + 2*HW };
    float* pbuf[2] = { pbase, pbase + 4*HW };

    k_init<<<NB4, NT>>>(x, ubuf[1]);

    for (int t = 1; t <= 9; t++) {
        k_reduce<<<NBR, NTR>>>(ubuf[t & 1]);
        float* uo = (t == 9) ? out : ubuf[(t + 1) & 1];
        if (t == 1)
            k_fused<0><<<NB4, NT>>>(ubuf[1], uo, nullptr, pbuf[1]);
        else if (t < 9)
            k_fused<1><<<NB4, NT>>>(ubuf[t & 1], uo, pbuf[(t + 1) & 1], pbuf[t & 1]);
        else
            k_fused<2><<<NB4, NT>>>(ubuf[t & 1], uo, pbuf[(t + 1) & 1], nullptr);
    }
}

// round 15
// speedup vs baseline: 1.1558x; 1.0158x over previous
#include <cuda_runtime.h>

#define HH 1024
#define WW 1024
#define HW (HH*WW)
#define NT 256
#define NB4 (HW/4/NT)     // 1024 blocks: init, fused (4 px/thread)
#define NTR 256
#define NBR (HW/8/NTR)    // 512 blocks: reduce (8 px/thread)

// ---------------- constants ----------------
__constant__ float c_lam;
__constant__ float c_tau;
__constant__ float c_th;

// ---------------- device scratch ----------------
__device__ __align__(16) float g_rhoc[HW];
__device__ __align__(16) float g_gi0[HW];
__device__ __align__(16) float g_gi1[HW];
__device__ __align__(16) float g_u[2][2*HW];
__device__ __align__(16) float g_p[2][4*HW];
__device__ float g_partial[NB4];
__device__ unsigned int g_count;
__device__ float g_S;

__device__ __forceinline__ float4 ldg4(const float* p) { return *(const float4*)p; }
__device__ __forceinline__ float2 ldg2(const float* p) { return *(const float2*)p; }

// 4x256 tile mapping (256-thread kernels, 4 px/thread in-row)
__device__ __forceinline__ void tile_map256(int& y, int& x0, int& pix) {
    int ty = blockIdx.x >> 2;
    int tx = (blockIdx.x & 3) << 8;
    y  = (ty << 2) + (threadIdx.x >> 6);
    x0 = tx + ((threadIdx.x & 63) << 2);
    pix = (y << 10) + x0;
}

// Separable sobel: col pass s_c = t0+2t1+t2, d_c = t0-t2;
// gx = s_{c-1}-s_{c+1}; gy = d_{c-1}+2d_c+d_{c+1}

// ---------------- K0: rho_c, grad_im, AND u_1 = v(u=0) ----------------
__global__ void __launch_bounds__(NT) k_init(const float* __restrict__ x, float* __restrict__ uout) {
    int t4 = blockIdx.x * NT + threadIdx.x;
    int pix = t4 * 4;
    int y = pix >> 10, x0 = pix & (WW - 1);
    const float* __restrict__ x1 = x + HW;

    float s[6], d[6];
    #pragma unroll
    for (int r = 0; r < 3; r++) {
        int yy = y - 1 + r; bool vy = (yy >= 0 && yy < HH);
        const float* row = x1 + yy * WW;
        float l = (vy && x0 > 0) ? row[x0 - 1] : 0.f;
        float4 b = vy ? ldg4(row + x0) : make_float4(0.f,0.f,0.f,0.f);
        float rg = (vy && x0 < WW - 4) ? row[x0 + 4] : 0.f;
        float rw[6] = {l, b.x, b.y, b.z, b.w, rg};
        #pragma unroll
        for (int j = 0; j < 6; j++) {
            if (r == 0)      { s[j] = rw[j];        d[j] = rw[j]; }
            else if (r == 1) { s[j] += 2.f * rw[j]; }
            else             { s[j] += rw[j];       d[j] -= rw[j]; }
        }
    }

    float4 xc0 = ldg4(x + pix);
    float4 xc1 = ldg4(x1 + pix);
    float4 RC = make_float4(xc1.x-xc0.x, xc1.y-xc0.y, xc1.z-xc0.z, xc1.w-xc0.w);
    *(float4*)(g_rhoc + pix) = RC;

    float4 A, B;
    float* Ap = &A.x; float* Bp = &B.x; const float* rc = &RC.x;
    #pragma unroll
    for (int i = 0; i < 4; i++) {
        Ap[i] = s[i] - s[i + 2];
        Bp[i] = d[i] + 2.f * d[i + 1] + d[i + 2];
    }
    *(float4*)(g_gi0 + pix) = A;
    *(float4*)(g_gi1 + pix) = B;

    float tl = c_th * c_lam;
    float o0[4], o1[4];
    #pragma unroll
    for (int i = 0; i < 4; i++) {
        float gi0 = Ap[i], gi1 = Bp[i];
        float nrm = gi0*gi0 + gi1*gi1;
        float rho = rc[i];
        float a = fabsf(rho);
        float thv = tl * nrm;
        float a0 = 0.f, a1 = 0.f;
        if (a < thv) {
            float q = rho / nrm;
            a0 = -q * gi0; a1 = -q * gi1;
        } else if (a > thv) {
            float sg = (rho > 0.f) ? 1.f : ((rho < 0.f) ? -1.f : 0.f);
            float c = tl * sg;
            a0 = -c * gi0; a1 = -c * gi1;
        }
        o0[i] = a0; o1[i] = a1;
    }
    *(float4*)(uout + pix)      = make_float4(o0[0],o0[1],o0[2],o0[3]);
    *(float4*)(uout + HW + pix) = make_float4(o1[0],o1[1],o1[2],o1[3]);

    if (pix == 0) g_count = 0u;
}

// ---------------- K_R: S = sum |sobel(u)|, 8 px/thread, rolling window ----------------
__global__ void __launch_bounds__(NTR) k_reduce(const float* __restrict__ u) {
    int bx = (blockIdx.x & 3) << 8;
    int by = (blockIdx.x >> 2) << 3;
    int tx = threadIdx.x & 63;
    int ty = threadIdx.x >> 6;
    int x0 = bx + (tx << 2);
    int y0 = by + (ty << 1);
    bool hL = (x0 > 0), hR = (x0 < WW - 4);

    float acc = 0.f;
    #pragma unroll
    for (int comp = 0; comp < 2; comp++) {
        const float* __restrict__ up = u + comp * HW;
        float w[3][6];
        #pragma unroll
        for (int rr = 0; rr < 2; rr++) {
            int yy = y0 - 1 + rr;
            bool vy = (yy >= 0 && yy < HH);
            const float* row = up + yy * WW;
            float l = (vy && hL) ? row[x0 - 1] : 0.f;
            float4 b = vy ? ldg4(row + x0) : make_float4(0.f,0.f,0.f,0.f);
            float rg = (vy && hR) ? row[x0 + 4] : 0.f;
            w[rr][0]=l; w[rr][1]=b.x; w[rr][2]=b.y; w[rr][3]=b.z; w[rr][4]=b.w; w[rr][5]=rg;
        }
        #pragma unroll
        for (int r = 0; r < 2; r++) {
            int yy = y0 + 1 + r;
            bool vy = (yy < HH);
            const float* row = up + yy * WW;
            float l = (vy && hL) ? row[x0 - 1] : 0.f;
            float4 b = vy ? ldg4(row + x0) : make_float4(0.f,0.f,0.f,0.f);
            float rg = (vy && hR) ? row[x0 + 4] : 0.f;
            int sb = (r + 2) % 3;
            w[sb][0]=l; w[sb][1]=b.x; w[sb][2]=b.y; w[sb][3]=b.z; w[sb][4]=b.w; w[sb][5]=rg;

            int st = r % 3, sm_ = (r + 1) % 3;
            float s[6], d[6];
            #pragma unroll
            for (int j = 0; j < 6; j++) {
                s[j] = w[st][j] + 2.f * w[sm_][j] + w[sb][j];
                d[j] = w[st][j] - w[sb][j];
            }
            #pragma unroll
            for (int i = 0; i < 4; i++)
                acc += fabsf(s[i] - s[i + 2]) + fabsf(d[i] + 2.f * d[i + 1] + d[i + 2]);
        }
    }

    __shared__ float sm[NTR];
    int tid = threadIdx.x;
    sm[tid] = acc;
    __syncthreads();
    for (int s = NTR / 2; s > 0; s >>= 1) {
        if (tid < s) sm[tid] += sm[tid + s];
        __syncthreads();
    }
    __shared__ bool isLast;
    if (tid == 0) {
        g_partial[blockIdx.x] = sm[0];
        __threadfence();
        unsigned prev = atomicAdd(&g_count, 1u);
        isLast = (prev == gridDim.x - 1);
    }
    __syncthreads();
    if (isLast && tid < 32) {
        float s = 0.f;
        for (int i = tid; i < (int)gridDim.x; i += 32) s += g_partial[i];
        #pragma unroll
        for (int o = 16; o > 0; o >>= 1) s += __shfl_down_sync(0xffffffffu, s, o);
        if (tid == 0) { g_S = s; g_count = 0u; }
    }
}

// ---------------- K_F: fused, smem hand-off of up-halo np2/np3 ----------------
// MODE 0: t==1 (p_in == 0). MODE 1: mid. MODE 2: last (no p write).
template<int MODE>
__global__ void __launch_bounds__(NT, 4) k_fused(const float* __restrict__ uin, float* __restrict__ uout,
                        const float* __restrict__ pin, float* __restrict__ pout) {
    __shared__ float sp2[4][256];
    __shared__ float sp3[4][256];

    int y, x0, pix;
    tile_map256(y, x0, pix);
    int tyl = threadIdx.x >> 6;          // row within block tile (0..3)
    int cl  = (threadIdx.x & 63) << 2;   // col within block tile (0..252)

    const float theta = c_th;
    const float tl = theta * c_lam;
    const float rr = c_tau / theta;
    const float inv = 1.f / (1.f + rr * g_S);

    // ---- u0 component: cols x0-2..x0+5 (8), rows y-1..y+1 ----
    float s0[8], d0[8];
    float u0c[4];
    #pragma unroll
    for (int r = 0; r < 3; r++) {
        int yy = y - 1 + r; bool vy = (yy >= 0 && yy < HH);
        const float* row = uin + yy * WW;
        float2 a = (vy && x0 > 0) ? ldg2(row + x0 - 2) : make_float2(0.f,0.f);
        float4 b = vy ? ldg4(row + x0) : make_float4(0.f,0.f,0.f,0.f);
        float2 c = (vy && x0 < WW - 4) ? ldg2(row + x0 + 4) : make_float2(0.f,0.f);
        float rw[8] = {a.x, a.y, b.x, b.y, b.z, b.w, c.x, c.y};
        if (r == 1) { u0c[0]=rw[2]; u0c[1]=rw[3]; u0c[2]=rw[4]; u0c[3]=rw[5]; }
        #pragma unroll
        for (int j = 0; j < 8; j++) {
            if (r == 0)      { s0[j] = rw[j];        d0[j] = rw[j]; }
            else if (r == 1) { s0[j] += 2.f * rw[j]; }
            else             { s0[j] += rw[j];       d0[j] -= rw[j]; }
        }
    }
    float G00[4], G01[4];
    #pragma unroll
    for (int i = 0; i < 4; i++) {
        G00[i] = s0[i + 1] - s0[i + 3];
        G01[i] = d0[i + 1] + 2.f * d0[i + 2] + d0[i + 3];
    }
    float L00 = s0[0] - s0[2];
    float L01 = d0[0] + 2.f * d0[1] + d0[2];

    // ---- u1 component: own sobel needs rows y-1..y+1; cols x0-1..x0+4 ----
    float so[6], dn[6];
    float u1c[4];
    const float* __restrict__ uin1 = uin + HW;
    #pragma unroll
    for (int r = 0; r < 3; r++) {
        int yy = y - 1 + r; bool vy = (yy >= 0 && yy < HH);
        const float* row = uin1 + yy * WW;
        float l = (vy && x0 > 0) ? row[x0 - 1] : 0.f;
        float4 b = vy ? ldg4(row + x0) : make_float4(0.f,0.f,0.f,0.f);
        float rg = (vy && x0 < WW - 4) ? row[x0 + 4] : 0.f;
        float rw[6] = {l, b.x, b.y, b.z, b.w, rg};
        if (r == 1) { u1c[0]=rw[1]; u1c[1]=rw[2]; u1c[2]=rw[3]; u1c[3]=rw[4]; }
        #pragma unroll
        for (int j = 0; j < 6; j++) {
            if (r == 0)      { so[j] = rw[j];        dn[j] = rw[j]; }
            else if (r == 1) { so[j] += 2.f * rw[j]; }
            else             { so[j] += rw[j];       dn[j] -= rw[j]; }
        }
    }
    float G10[4], G11[4];
    #pragma unroll
    for (int i = 0; i < 4; i++) {
        G10[i] = so[i] - so[i + 2];
        G11[i] = dn[i] + 2.f * dn[i + 1] + dn[i + 2];
    }

    // ---- up-halo sobels (U): only block's top row of threads (warp-uniform branch) ----
    float U10[4], U11[4];
    bool hasU = (y > 0);
    if (tyl == 0) {
        // rows y-2..y, cols x0-1..x0+4 ; rows y-1,y already loaded? (kept simple: reload 3 rows)
        float su[6], du[6];
        #pragma unroll
        for (int r = 0; r < 3; r++) {
            int yy = y - 2 + r; bool vy = (yy >= 0 && yy < HH);
            const float* row = uin1 + yy * WW;
            float l = (vy && x0 > 0) ? row[x0 - 1] : 0.f;
            float4 b = vy ? ldg4(row + x0) : make_float4(0.f,0.f,0.f,0.f);
            float rg = (vy && x0 < WW - 4) ? row[x0 + 4] : 0.f;
            float rw[6] = {l, b.x, b.y, b.z, b.w, rg};
            #pragma unroll
            for (int j = 0; j < 6; j++) {
                if (r == 0)      { su[j] = rw[j];        du[j] = rw[j]; }
                else if (r == 1) { su[j] += 2.f * rw[j]; }
                else             { su[j] += rw[j];       du[j] -= rw[j]; }
            }
        }
        #pragma unroll
        for (int i = 0; i < 4; i++) {
            U10[i] = su[i] - su[i + 2];
            U11[i] = du[i] + 2.f * du[i + 1] + du[i + 2];
        }
    }

    // ---- pointwise v update ----
    float4 GI0 = ldg4(g_gi0 + pix);
    float4 GI1 = ldg4(g_gi1 + pix);
    float4 RC  = ldg4(g_rhoc + pix);
    const float* gi0 = &GI0.x; const float* gi1 = &GI1.x; const float* rc = &RC.x;

    float v0[4], v1[4];
    #pragma unroll
    for (int i = 0; i < 4; i++) {
        float nrm = gi0[i]*gi0[i] + gi1[i]*gi1[i];
        float rho = rc[i] + gi0[i]*u0c[i] + gi1[i]*u1c[i];
        float a = fabsf(rho);
        float thv = tl * nrm;
        float a0 = u0c[i], a1 = u1c[i];
        if (a < thv) {
            float q = rho / nrm;
            a0 -= q * gi0[i]; a1 -= q * gi1[i];
        } else if (a > thv) {
            float sg = (rho > 0.f) ? 1.f : ((rho < 0.f) ? -1.f : 0.f);
            float c = tl * sg;
            a0 -= c * gi0[i]; a1 -= c * gi1[i];
        }
        v0[i] = a0; v1[i] = a1;
    }

    bool hasL = (x0 > 0);

    float np0[4], np1[4], np2[4], np3[4];
    float lft0, lft1;
    float hU2[4], hU3[4];   // halo np2/np3 for tyl==0 only

    if (MODE == 0) {
        #pragma unroll
        for (int i = 0; i < 4; i++) {
            np0[i] = rr * G00[i] * inv;
            np1[i] = rr * G01[i] * inv;
            np2[i] = rr * G10[i] * inv;
            np3[i] = rr * G11[i] * inv;
        }
        lft0 = hasL ? rr * L00 * inv : 0.f;
        lft1 = hasL ? rr * L01 * inv : 0.f;
        if (tyl == 0) {
            #pragma unroll
            for (int i = 0; i < 4; i++) {
                hU2[i] = hasU ? rr * U10[i] * inv : 0.f;
                hU3[i] = hasU ? rr * U11[i] * inv : 0.f;
            }
        }
    } else {
        float4 P0 = ldg4(pin + pix);
        float4 P1 = ldg4(pin + HW + pix);
        float4 P2 = ldg4(pin + 2*HW + pix);
        float4 P3 = ldg4(pin + 3*HW + pix);
        const float* p0 = &P0.x; const float* p1 = &P1.x;
        const float* p2 = &P2.x; const float* p3 = &P3.x;

        float pl0 = hasL ? pin[pix - 1]      : 0.f;
        float pl1 = hasL ? pin[HW + pix - 1] : 0.f;

        #pragma unroll
        for (int i = 0; i < 4; i++) {
            np0[i] = (p0[i] + rr * G00[i]) * inv;
            np1[i] = (p1[i] + rr * G01[i]) * inv;
            np2[i] = (p2[i] + rr * G10[i]) * inv;
            np3[i] = (p3[i] + rr * G11[i]) * inv;
        }
        lft0 = hasL ? (pl0 + rr * L00) * inv : 0.f;
        lft1 = hasL ? (pl1 + rr * L01) * inv : 0.f;

        if (tyl == 0) {
            float4 PU2 = hasU ? ldg4(pin + 2*HW + pix - WW) : make_float4(0.f,0.f,0.f,0.f);
            float4 PU3 = hasU ? ldg4(pin + 3*HW + pix - WW) : make_float4(0.f,0.f,0.f,0.f);
            const float* pu2 = &PU2.x; const float* pu3 = &PU3.x;
            #pragma unroll
            for (int i = 0; i < 4; i++) {
                hU2[i] = hasU ? (pu2[i] + rr * U10[i]) * inv : 0.f;
                hU3[i] = hasU ? (pu3[i] + rr * U11[i]) * inv : 0.f;
            }
        }
    }

    // publish own np2/np3 for the row below
    *(float4*)(&sp2[tyl][cl]) = make_float4(np2[0], np2[1], np2[2], np2[3]);
    *(float4*)(&sp3[tyl][cl]) = make_float4(np3[0], np3[1], np3[2], np3[3]);
    __syncthreads();

    float pU2v[4], pU3v[4];
    if (tyl > 0) {
        float4 q2 = *(float4*)(&sp2[tyl - 1][cl]);
        float4 q3 = *(float4*)(&sp3[tyl - 1][cl]);
        pU2v[0]=q2.x; pU2v[1]=q2.y; pU2v[2]=q2.z; pU2v[3]=q2.w;
        pU3v[0]=q3.x; pU3v[1]=q3.y; pU3v[2]=q3.z; pU3v[3]=q3.w;
    } else {
        #pragma unroll
        for (int i = 0; i < 4; i++) { pU2v[i] = hU2[i]; pU3v[i] = hU3[i]; }
    }

    // wx = wy = (1,1): divergence = left + own + up + own
    float o0[4], o1[4];
    #pragma unroll
    for (int i = 0; i < 4; i++) {
        float pL0 = (i == 0) ? lft0 : np0[i-1];
        float pL1 = (i == 0) ? lft1 : np1[i-1];
        float d0v = pL0 + np0[i] + pU2v[i] + np2[i];
        float d1v = pL1 + np1[i] + pU3v[i] + np3[i];
        o0[i] = v0[i] + theta * d0v;
        o1[i] = v1[i] + theta * d1v;
    }

    *(float4*)(uout + pix)      = make_float4(o0[0],o0[1],o0[2],o0[3]);
    *(float4*)(uout + HW + pix) = make_float4(o1[0],o1[1],o1[2],o1[3]);

    if (MODE != 2) {
        *(float4*)(pout + pix)        = make_float4(np0[0],np0[1],np0[2],np0[3]);
        *(float4*)(pout + HW + pix)   = make_float4(np1[0],np1[1],np1[2],np1[3]);
        *(float4*)(pout + 2*HW + pix) = make_float4(np2[0],np2[1],np2[2],np2[3]);
        *(float4*)(pout + 3*HW + pix) = make_float4(np3[0],np3[1],np3[2],np3[3]);
    }
}

// ---------------- launch ----------------
extern "C" void kernel_launch(void* const* d_in, const int* in_sizes, int n_in,
                              void* d_out, int out_size) {
    const float* x   = (const float*)d_in[0];
    const float* lam = (const float*)d_in[4];
    const float* tau = (const float*)d_in[5];
    const float* th  = (const float*)d_in[6];
    float* out = (float*)d_out;

    cudaMemcpyToSymbolAsync(c_lam, lam, sizeof(float), 0, cudaMemcpyDeviceToDevice);
    cudaMemcpyToSymbolAsync(c_tau, tau, sizeof(float), 0, cudaMemcpyDeviceToDevice);
    cudaMemcpyToSymbolAsync(c_th,  th,  sizeof(float), 0, cudaMemcpyDeviceToDevice);

    float* ubase; cudaGetSymbolAddress((void**)&ubase, g_u);
    float* pbase; cudaGetSymbolAddress((void**)&pbase, g_p);
    float* ubuf[2] = { ubase, ubase + 2*HW };
    float* pbuf[2] = { pbase, pbase + 4*HW };

    k_init<<<NB4, NT>>>(x, ubuf[1]);

    for (int t = 1; t <= 9; t++) {
        k_reduce<<<NBR, NTR>>>(ubuf[t & 1]);
        float* uo = (t == 9) ? out : ubuf[(t + 1) & 1];
        if (t == 1)
            k_fused<0><<<NB4, NT>>>(ubuf[1], uo, nullptr, pbuf[1]);
        else if (t < 9)
            k_fused<1><<<NB4, NT>>>(ubuf[t & 1], uo, pbuf[(t + 1) & 1], pbuf[t & 1]);
        else
            k_fused<2><<<NB4, NT>>>(ubuf[t & 1], uo, pbuf[(t + 1) & 1], nullptr);
    }
}

// round 16
// speedup vs baseline: 1.1643x; 1.0074x over previous
#include <cuda_runtime.h>

#define HH 1024
#define WW 1024
#define HW (HH*WW)
#define NT 256
#define NB4 (HW/4/NT)     // 1024 blocks: init, fused (4 px/thread)
#define NTR 256
#define NBR (HW/8/NTR)    // 512 blocks: reduce (8 px/thread)

// ---------------- constants ----------------
__constant__ float c_lam;
__constant__ float c_tau;
__constant__ float c_th;

// ---------------- device scratch ----------------
__device__ __align__(16) float g_rhoc[HW];
__device__ __align__(16) float g_gi0[HW];
__device__ __align__(16) float g_gi1[HW];
__device__ __align__(16) float g_u[2][2*HW];
__device__ __align__(16) float g_p[2][4*HW];
__device__ float g_partial[NB4];
__device__ unsigned int g_count;
__device__ float g_S;

__device__ __forceinline__ float4 ldg4(const float* p) { return *(const float4*)p; }
__device__ __forceinline__ float2 ldg2(const float* p) { return *(const float2*)p; }

// 4x256 tile mapping (256-thread kernels, 4 px/thread in-row)
__device__ __forceinline__ void tile_map256(int& y, int& x0, int& pix) {
    int ty = blockIdx.x >> 2;
    int tx = (blockIdx.x & 3) << 8;
    y  = (ty << 2) + (threadIdx.x >> 6);
    x0 = tx + ((threadIdx.x & 63) << 2);
    pix = (y << 10) + x0;
}

// Separable sobel: col pass s_c = t0+2t1+t2, d_c = t0-t2;
// gx = s_{c-1}-s_{c+1}; gy = d_{c-1}+2d_c+d_{c+1}

// ---------------- K0: rho_c, grad_im, AND u_1 = v(u=0) ----------------
__global__ void __launch_bounds__(NT) k_init(const float* __restrict__ x, float* __restrict__ uout) {
    int t4 = blockIdx.x * NT + threadIdx.x;
    int pix = t4 * 4;
    int y = pix >> 10, x0 = pix & (WW - 1);
    const float* __restrict__ x1 = x + HW;

    float s[6], d[6];
    #pragma unroll
    for (int r = 0; r < 3; r++) {
        int yy = y - 1 + r; bool vy = (yy >= 0 && yy < HH);
        const float* row = x1 + yy * WW;
        float l = (vy && x0 > 0) ? row[x0 - 1] : 0.f;
        float4 b = vy ? ldg4(row + x0) : make_float4(0.f,0.f,0.f,0.f);
        float rg = (vy && x0 < WW - 4) ? row[x0 + 4] : 0.f;
        float rw[6] = {l, b.x, b.y, b.z, b.w, rg};
        #pragma unroll
        for (int j = 0; j < 6; j++) {
            if (r == 0)      { s[j] = rw[j];        d[j] = rw[j]; }
            else if (r == 1) { s[j] += 2.f * rw[j]; }
            else             { s[j] += rw[j];       d[j] -= rw[j]; }
        }
    }

    float4 xc0 = ldg4(x + pix);
    float4 xc1 = ldg4(x1 + pix);
    float4 RC = make_float4(xc1.x-xc0.x, xc1.y-xc0.y, xc1.z-xc0.z, xc1.w-xc0.w);
    *(float4*)(g_rhoc + pix) = RC;

    float4 A, B;
    float* Ap = &A.x; float* Bp = &B.x; const float* rc = &RC.x;
    #pragma unroll
    for (int i = 0; i < 4; i++) {
        Ap[i] = s[i] - s[i + 2];
        Bp[i] = d[i] + 2.f * d[i + 1] + d[i + 2];
    }
    *(float4*)(g_gi0 + pix) = A;
    *(float4*)(g_gi1 + pix) = B;

    float tl = c_th * c_lam;
    float o0[4], o1[4];
    #pragma unroll
    for (int i = 0; i < 4; i++) {
        float gi0 = Ap[i], gi1 = Bp[i];
        float nrm = gi0*gi0 + gi1*gi1;
        float rho = rc[i];
        float a = fabsf(rho);
        float thv = tl * nrm;
        float a0 = 0.f, a1 = 0.f;
        if (a < thv) {
            float q = rho / nrm;
            a0 = -q * gi0; a1 = -q * gi1;
        } else if (a > thv) {
            float sg = (rho > 0.f) ? 1.f : ((rho < 0.f) ? -1.f : 0.f);
            float c = tl * sg;
            a0 = -c * gi0; a1 = -c * gi1;
        }
        o0[i] = a0; o1[i] = a1;
    }
    *(float4*)(uout + pix)      = make_float4(o0[0],o0[1],o0[2],o0[3]);
    *(float4*)(uout + HW + pix) = make_float4(o1[0],o1[1],o1[2],o1[3]);

    if (pix == 0) g_count = 0u;
}

// ---------------- K_R: S = sum |sobel(u)|, 8 px/thread, rolling window ----------------
__global__ void __launch_bounds__(NTR) k_reduce(const float* __restrict__ u) {
    int bx = (blockIdx.x & 3) << 8;
    int by = (blockIdx.x >> 2) << 3;
    int tx = threadIdx.x & 63;
    int ty = threadIdx.x >> 6;
    int x0 = bx + (tx << 2);
    int y0 = by + (ty << 1);
    bool hL = (x0 > 0), hR = (x0 < WW - 4);

    float acc = 0.f;
    #pragma unroll
    for (int comp = 0; comp < 2; comp++) {
        const float* __restrict__ up = u + comp * HW;
        float w[3][6];
        #pragma unroll
        for (int rr = 0; rr < 2; rr++) {
            int yy = y0 - 1 + rr;
            bool vy = (yy >= 0 && yy < HH);
            const float* row = up + yy * WW;
            float l = (vy && hL) ? row[x0 - 1] : 0.f;
            float4 b = vy ? ldg4(row + x0) : make_float4(0.f,0.f,0.f,0.f);
            float rg = (vy && hR) ? row[x0 + 4] : 0.f;
            w[rr][0]=l; w[rr][1]=b.x; w[rr][2]=b.y; w[rr][3]=b.z; w[rr][4]=b.w; w[rr][5]=rg;
        }
        #pragma unroll
        for (int r = 0; r < 2; r++) {
            int yy = y0 + 1 + r;
            bool vy = (yy < HH);
            const float* row = up + yy * WW;
            float l = (vy && hL) ? row[x0 - 1] : 0.f;
            float4 b = vy ? ldg4(row + x0) : make_float4(0.f,0.f,0.f,0.f);
            float rg = (vy && hR) ? row[x0 + 4] : 0.f;
            int sb = (r + 2) % 3;
            w[sb][0]=l; w[sb][1]=b.x; w[sb][2]=b.y; w[sb][3]=b.z; w[sb][4]=b.w; w[sb][5]=rg;

            int st = r % 3, sm_ = (r + 1) % 3;
            float s[6], d[6];
            #pragma unroll
            for (int j = 0; j < 6; j++) {
                s[j] = w[st][j] + 2.f * w[sm_][j] + w[sb][j];
                d[j] = w[st][j] - w[sb][j];
            }
            #pragma unroll
            for (int i = 0; i < 4; i++)
                acc += fabsf(s[i] - s[i + 2]) + fabsf(d[i] + 2.f * d[i + 1] + d[i + 2]);
        }
    }

    __shared__ float sm[NTR];
    int tid = threadIdx.x;
    sm[tid] = acc;
    __syncthreads();
    for (int s = NTR / 2; s > 0; s >>= 1) {
        if (tid < s) sm[tid] += sm[tid + s];
        __syncthreads();
    }
    __shared__ bool isLast;
    if (tid == 0) {
        g_partial[blockIdx.x] = sm[0];
        __threadfence();
        unsigned prev = atomicAdd(&g_count, 1u);
        isLast = (prev == gridDim.x - 1);
    }
    __syncthreads();
    if (isLast && tid < 32) {
        float s = 0.f;
        for (int i = tid; i < (int)gridDim.x; i += 32) s += g_partial[i];
        #pragma unroll
        for (int o = 16; o > 0; o >>= 1) s += __shfl_down_sync(0xffffffffu, s, o);
        if (tid == 0) { g_S = s; g_count = 0u; }
    }
}

// ---------------- K_F: fused, smem hand-off of up-halo np2/np3 AND left-halo np0/np1 ----------------
// MODE 0: t==1 (p_in == 0). MODE 1: mid. MODE 2: last (no p write).
template<int MODE>
__global__ void __launch_bounds__(NT, 4) k_fused(const float* __restrict__ uin, float* __restrict__ uout,
                        const float* __restrict__ pin, float* __restrict__ pout) {
    __shared__ float sp2[4][256];
    __shared__ float sp3[4][256];
    __shared__ float sl0[4][64];
    __shared__ float sl1[4][64];

    int y, x0, pix;
    tile_map256(y, x0, pix);
    int tyl = threadIdx.x >> 6;          // row within block tile (0..3)
    int txl = threadIdx.x & 63;          // col-group within block tile (0..63)
    int cl  = txl << 2;                  // col within block tile (0..252)

    const float theta = c_th;
    const float tl = theta * c_lam;
    const float rr = c_tau / theta;
    const float inv = 1.f / (1.f + rr * g_S);

    // ---- u0 component: cols x0-2..x0+5 (8), rows y-1..y+1 ----
    float s0[8], d0[8];
    float u0c[4];
    #pragma unroll
    for (int r = 0; r < 3; r++) {
        int yy = y - 1 + r; bool vy = (yy >= 0 && yy < HH);
        const float* row = uin + yy * WW;
        float2 a = (vy && x0 > 0) ? ldg2(row + x0 - 2) : make_float2(0.f,0.f);
        float4 b = vy ? ldg4(row + x0) : make_float4(0.f,0.f,0.f,0.f);
        float2 c = (vy && x0 < WW - 4) ? ldg2(row + x0 + 4) : make_float2(0.f,0.f);
        float rw[8] = {a.x, a.y, b.x, b.y, b.z, b.w, c.x, c.y};
        if (r == 1) { u0c[0]=rw[2]; u0c[1]=rw[3]; u0c[2]=rw[4]; u0c[3]=rw[5]; }
        #pragma unroll
        for (int j = 0; j < 8; j++) {
            if (r == 0)      { s0[j] = rw[j];        d0[j] = rw[j]; }
            else if (r == 1) { s0[j] += 2.f * rw[j]; }
            else             { s0[j] += rw[j];       d0[j] -= rw[j]; }
        }
    }
    float G00[4], G01[4];
    #pragma unroll
    for (int i = 0; i < 4; i++) {
        G00[i] = s0[i + 1] - s0[i + 3];
        G01[i] = d0[i + 1] + 2.f * d0[i + 2] + d0[i + 3];
    }

    // ---- u1 component: own sobel needs rows y-1..y+1; cols x0-1..x0+4 ----
    float so[6], dn[6];
    float u1c[4];
    const float* __restrict__ uin1 = uin + HW;
    #pragma unroll
    for (int r = 0; r < 3; r++) {
        int yy = y - 1 + r; bool vy = (yy >= 0 && yy < HH);
        const float* row = uin1 + yy * WW;
        float l = (vy && x0 > 0) ? row[x0 - 1] : 0.f;
        float4 b = vy ? ldg4(row + x0) : make_float4(0.f,0.f,0.f,0.f);
        float rg = (vy && x0 < WW - 4) ? row[x0 + 4] : 0.f;
        float rw[6] = {l, b.x, b.y, b.z, b.w, rg};
        if (r == 1) { u1c[0]=rw[1]; u1c[1]=rw[2]; u1c[2]=rw[3]; u1c[3]=rw[4]; }
        #pragma unroll
        for (int j = 0; j < 6; j++) {
            if (r == 0)      { so[j] = rw[j];        dn[j] = rw[j]; }
            else if (r == 1) { so[j] += 2.f * rw[j]; }
            else             { so[j] += rw[j];       dn[j] -= rw[j]; }
        }
    }
    float G10[4], G11[4];
    #pragma unroll
    for (int i = 0; i < 4; i++) {
        G10[i] = so[i] - so[i + 2];
        G11[i] = dn[i] + 2.f * dn[i + 1] + dn[i + 2];
    }

    // ---- up-halo sobels (U): only block's top thread-row ----
    float U10[4], U11[4];
    bool hasU = (y > 0);
    if (tyl == 0) {
        float su[6], du[6];
        #pragma unroll
        for (int r = 0; r < 3; r++) {
            int yy = y - 2 + r; bool vy = (yy >= 0 && yy < HH);
            const float* row = uin1 + yy * WW;
            float l = (vy && x0 > 0) ? row[x0 - 1] : 0.f;
            float4 b = vy ? ldg4(row + x0) : make_float4(0.f,0.f,0.f,0.f);
            float rg = (vy && x0 < WW - 4) ? row[x0 + 4] : 0.f;
            float rw[6] = {l, b.x, b.y, b.z, b.w, rg};
            #pragma unroll
            for (int j = 0; j < 6; j++) {
                if (r == 0)      { su[j] = rw[j];        du[j] = rw[j]; }
                else if (r == 1) { su[j] += 2.f * rw[j]; }
                else             { su[j] += rw[j];       du[j] -= rw[j]; }
            }
        }
        #pragma unroll
        for (int i = 0; i < 4; i++) {
            U10[i] = su[i] - su[i + 2];
            U11[i] = du[i] + 2.f * du[i + 1] + du[i + 2];
        }
    }

    // ---- left-halo sobels (L): only block's left thread-column ----
    float L00, L01;
    bool hasL = (x0 > 0);
    if (txl == 0) {
        L00 = s0[0] - s0[2];
        L01 = d0[0] + 2.f * d0[1] + d0[2];
    }

    // ---- pointwise v update ----
    float4 GI0 = ldg4(g_gi0 + pix);
    float4 GI1 = ldg4(g_gi1 + pix);
    float4 RC  = ldg4(g_rhoc + pix);
    const float* gi0 = &GI0.x; const float* gi1 = &GI1.x; const float* rc = &RC.x;

    float v0[4], v1[4];
    #pragma unroll
    for (int i = 0; i < 4; i++) {
        float nrm = gi0[i]*gi0[i] + gi1[i]*gi1[i];
        float rho = rc[i] + gi0[i]*u0c[i] + gi1[i]*u1c[i];
        float a = fabsf(rho);
        float thv = tl * nrm;
        float a0 = u0c[i], a1 = u1c[i];
        if (a < thv) {
            float q = rho / nrm;
            a0 -= q * gi0[i]; a1 -= q * gi1[i];
        } else if (a > thv) {
            float sg = (rho > 0.f) ? 1.f : ((rho < 0.f) ? -1.f : 0.f);
            float c = tl * sg;
            a0 -= c * gi0[i]; a1 -= c * gi1[i];
        }
        v0[i] = a0; v1[i] = a1;
    }

    float np0[4], np1[4], np2[4], np3[4];
    float lft0 = 0.f, lft1 = 0.f;
    float hU2[4], hU3[4];

    if (MODE == 0) {
        #pragma unroll
        for (int i = 0; i < 4; i++) {
            np0[i] = rr * G00[i] * inv;
            np1[i] = rr * G01[i] * inv;
            np2[i] = rr * G10[i] * inv;
            np3[i] = rr * G11[i] * inv;
        }
        if (txl == 0) {
            lft0 = hasL ? rr * L00 * inv : 0.f;
            lft1 = hasL ? rr * L01 * inv : 0.f;
        }
        if (tyl == 0) {
            #pragma unroll
            for (int i = 0; i < 4; i++) {
                hU2[i] = hasU ? rr * U10[i] * inv : 0.f;
                hU3[i] = hasU ? rr * U11[i] * inv : 0.f;
            }
        }
    } else {
        float4 P0 = ldg4(pin + pix);
        float4 P1 = ldg4(pin + HW + pix);
        float4 P2 = ldg4(pin + 2*HW + pix);
        float4 P3 = ldg4(pin + 3*HW + pix);
        const float* p0 = &P0.x; const float* p1 = &P1.x;
        const float* p2 = &P2.x; const float* p3 = &P3.x;

        #pragma unroll
        for (int i = 0; i < 4; i++) {
            np0[i] = (p0[i] + rr * G00[i]) * inv;
            np1[i] = (p1[i] + rr * G01[i]) * inv;
            np2[i] = (p2[i] + rr * G10[i]) * inv;
            np3[i] = (p3[i] + rr * G11[i]) * inv;
        }

        if (txl == 0) {
            float pl0 = hasL ? pin[pix - 1]      : 0.f;
            float pl1 = hasL ? pin[HW + pix - 1] : 0.f;
            lft0 = hasL ? (pl0 + rr * L00) * inv : 0.f;
            lft1 = hasL ? (pl1 + rr * L01) * inv : 0.f;
        }

        if (tyl == 0) {
            float4 PU2 = hasU ? ldg4(pin + 2*HW + pix - WW) : make_float4(0.f,0.f,0.f,0.f);
            float4 PU3 = hasU ? ldg4(pin + 3*HW + pix - WW) : make_float4(0.f,0.f,0.f,0.f);
            const float* pu2 = &PU2.x; const float* pu3 = &PU3.x;
            #pragma unroll
            for (int i = 0; i < 4; i++) {
                hU2[i] = hasU ? (pu2[i] + rr * U10[i]) * inv : 0.f;
                hU3[i] = hasU ? (pu3[i] + rr * U11[i]) * inv : 0.f;
            }
        }
    }

    // publish: own np2/np3 (for row below), own np0[3]/np1[3] (for right neighbor)
    *(float4*)(&sp2[tyl][cl]) = make_float4(np2[0], np2[1], np2[2], np2[3]);
    *(float4*)(&sp3[tyl][cl]) = make_float4(np3[0], np3[1], np3[2], np3[3]);
    sl0[tyl][txl] = np0[3];
    sl1[tyl][txl] = np1[3];
    __syncthreads();

    float pU2v[4], pU3v[4];
    if (tyl > 0) {
        float4 q2 = *(float4*)(&sp2[tyl - 1][cl]);
        float4 q3 = *(float4*)(&sp3[tyl - 1][cl]);
        pU2v[0]=q2.x; pU2v[1]=q2.y; pU2v[2]=q2.z; pU2v[3]=q2.w;
        pU3v[0]=q3.x; pU3v[1]=q3.y; pU3v[2]=q3.z; pU3v[3]=q3.w;
    } else {
        #pragma unroll
        for (int i = 0; i < 4; i++) { pU2v[i] = hU2[i]; pU3v[i] = hU3[i]; }
    }
    if (txl > 0) {
        lft0 = sl0[tyl][txl - 1];
        lft1 = sl1[tyl][txl - 1];
    }

    // wx = wy = (1,1): divergence = left + own + up + own
    float o0[4], o1[4];
    #pragma unroll
    for (int i = 0; i < 4; i++) {
        float pL0 = (i == 0) ? lft0 : np0[i-1];
        float pL1 = (i == 0) ? lft1 : np1[i-1];
        float d0v = pL0 + np0[i] + pU2v[i] + np2[i];
        float d1v = pL1 + np1[i] + pU3v[i] + np3[i];
        o0[i] = v0[i] + theta * d0v;
        o1[i] = v1[i] + theta * d1v;
    }

    *(float4*)(uout + pix)      = make_float4(o0[0],o0[1],o0[2],o0[3]);
    *(float4*)(uout + HW + pix) = make_float4(o1[0],o1[1],o1[2],o1[3]);

    if (MODE != 2) {
        *(float4*)(pout + pix)        = make_float4(np0[0],np0[1],np0[2],np0[3]);
        *(float4*)(pout + HW + pix)   = make_float4(np1[0],np1[1],np1[2],np1[3]);
        *(float4*)(pout + 2*HW + pix) = make_float4(np2[0],np2[1],np2[2],np2[3]);
        *(float4*)(pout + 3*HW + pix) = make_float4(np3[0],np3[1],np3[2],np3[3]);
    }
}

// ---------------- launch ----------------
extern "C" void kernel_launch(void* const* d_in, const int* in_sizes, int n_in,
                              void* d_out, int out_size) {
    const float* x   = (const float*)d_in[0];
    const float* lam = (const float*)d_in[4];
    const float* tau = (const float*)d_in[5];
    const float* th  = (const float*)d_in[6];
    float* out = (float*)d_out;

    cudaMemcpyToSymbolAsync(c_lam, lam, sizeof(float), 0, cudaMemcpyDeviceToDevice);
    cudaMemcpyToSymbolAsync(c_tau, tau, sizeof(float), 0, cudaMemcpyDeviceToDevice);
    cudaMemcpyToSymbolAsync(c_th,  th,  sizeof(float), 0, cudaMemcpyDeviceToDevice);

    float* ubase; cudaGetSymbolAddress((void**)&ubase, g_u);
    float* pbase; cudaGetSymbolAddress((void**)&pbase, g_p);
    float* ubuf[2] = { ubase, ubase + 2*HW };
    float* pbuf[2] = { pbase, pbase + 4*HW };

    k_init<<<NB4, NT>>>(x, ubuf[1]);

    for (int t = 1; t <= 9; t++) {
        k_reduce<<<NBR, NTR>>>(ubuf[t & 1]);
        float* uo = (t == 9) ? out : ubuf[(t + 1) & 1];
        if (t == 1)
            k_fused<0><<<NB4, NT>>>(ubuf[1], uo, nullptr, pbuf[1]);
        else if (t < 9)
            k_fused<1><<<NB4, NT>>>(ubuf[t & 1], uo, pbuf[(t + 1) & 1], pbuf[t & 1]);
        else
            k_fused<2><<<NB4, NT>>>(ubuf[t & 1], uo, pbuf[(t + 1) & 1], nullptr);
    }
}